// round 2
// baseline (speedup 1.0000x reference)
#include <cuda_runtime.h>
#include <cstdint>

// SimpleRetention — recurrent reformulation.
// B=32, S=1024, E=512, H=64, N_AGENTS=4, T=256, KAPPA=0.9
//
// Pipeline:
//   K0 decode_dones : detect dtype of `dones`, extract ts_dones = dones[:, ::4]
//   K1 proj         : q = query@W_Q, k = key@W_K, v = value@W_V  (fp32 tiled GEMM)
//   K2 scan         : gated linear recurrence over T, emits O and next_hstate

#define BB 32
#define SS 1024
#define EE 512
#define HH 64
#define TT 256
#define KAPPA 0.9f

// ---------------- device scratch (static allocation only) ----------------
__device__ float g_q[BB * SS * HH];   // 8 MB
__device__ float g_k[BB * SS * HH];   // 8 MB
__device__ float g_v[BB * SS * HH];   // 8 MB
__device__ unsigned char g_tsdone[BB * TT];

// ---------------- K0: decode dones (dtype-agnostic) ----------------
// Hypotheses: float32 (word 0x3F800000 for true), int32 (word 0/1),
// uint8/bool (bytes 0/1 -> words can look like e.g. 0x00010000).
// Scan only the first 8192 words (= 32768 bytes) — safe under every
// hypothesis since the smallest possible buffer is 32768 bytes (uint8).
__global__ void decode_dones_kernel(const void* __restrict__ dones) {
    __shared__ int s_f32, s_u8;
    if (threadIdx.x == 0) { s_f32 = 0; s_u8 = 0; }
    __syncthreads();
    const unsigned* w = (const unsigned*)dones;
    int lf = 0, lu = 0;
    for (int idx = threadIdx.x; idx < 8192; idx += 256) {
        unsigned x = w[idx];
        if (x == 0x3F800000u) lf = 1;
        else if (x > 1u) lu = 1;   // multi-byte packing => uint8
    }
    if (lf) s_f32 = 1;
    if (lu) s_u8 = 1;
    __syncthreads();
    int fmt = s_f32 ? 1 : (s_u8 ? 2 : 0);  // 0=int32, 1=float32, 2=uint8

    for (int idx = threadIdx.x; idx < BB * TT; idx += 256) {
        int b = idx >> 8;          // /256
        int t = idx & 255;
        int pos = b * SS + 4 * t;  // dones[b, 4t]
        unsigned char d;
        if (fmt == 2) d = (((const unsigned char*)dones)[pos] != 0);
        else          d = (w[pos] != 0u);   // works for int32 and f32 bits
        g_tsdone[idx] = d;
    }
}

// ---------------- K1: projection GEMM  Y[32768,64] = X[32768,512] @ W[512,64]
// BM=64, BN=64, BK=32, 256 threads, 4x4 register tile per thread. FMA-bound.
__global__ __launch_bounds__(256)
void proj_kernel(const float* __restrict__ in_key,
                 const float* __restrict__ in_query,
                 const float* __restrict__ in_value,
                 const float* __restrict__ Wq,
                 const float* __restrict__ Wk,
                 const float* __restrict__ Wv) {
    const float* X;
    const float* W;
    float* Y;
    switch (blockIdx.z) {
        case 0:  X = in_query; W = Wq; Y = g_q; break;
        case 1:  X = in_key;   W = Wk; Y = g_k; break;
        default: X = in_value; W = Wv; Y = g_v; break;
    }

    __shared__ float Xs[64][33];   // padded rows
    __shared__ float Ws[32][64];

    const int tid = threadIdx.x;
    const int tx = tid & 15;          // output col group (tx*4)
    const int ty = tid >> 4;          // output row group (ty*4)
    const int m0 = blockIdx.x * 64;

    float acc[4][4];
#pragma unroll
    for (int i = 0; i < 4; i++)
#pragma unroll
        for (int j = 0; j < 4; j++) acc[i][j] = 0.f;

    for (int kt = 0; kt < EE; kt += 32) {
        // load X tile: 64x32 floats = 512 float4, 2 per thread
#pragma unroll
        for (int r = 0; r < 2; r++) {
            int i4 = tid + r * 256;
            int row = i4 >> 3;             // /8
            int c4 = (i4 & 7) * 4;
            float4 xv = *(const float4*)&X[(size_t)(m0 + row) * EE + kt + c4];
            Xs[row][c4 + 0] = xv.x;
            Xs[row][c4 + 1] = xv.y;
            Xs[row][c4 + 2] = xv.z;
            Xs[row][c4 + 3] = xv.w;
        }
        // load W tile: 32x64 floats = 512 float4, 2 per thread
#pragma unroll
        for (int r = 0; r < 2; r++) {
            int i4 = tid + r * 256;
            int row = i4 >> 4;             // /16
            int c4 = (i4 & 15) * 4;
            *(float4*)&Ws[row][c4] = *(const float4*)&W[(size_t)(kt + row) * HH + c4];
        }
        __syncthreads();

#pragma unroll 8
        for (int kk = 0; kk < 32; kk++) {
            float a0 = Xs[ty * 4 + 0][kk];
            float a1 = Xs[ty * 4 + 1][kk];
            float a2 = Xs[ty * 4 + 2][kk];
            float a3 = Xs[ty * 4 + 3][kk];
            float4 bb = *(const float4*)&Ws[kk][tx * 4];
            acc[0][0] += a0 * bb.x; acc[0][1] += a0 * bb.y; acc[0][2] += a0 * bb.z; acc[0][3] += a0 * bb.w;
            acc[1][0] += a1 * bb.x; acc[1][1] += a1 * bb.y; acc[1][2] += a1 * bb.z; acc[1][3] += a1 * bb.w;
            acc[2][0] += a2 * bb.x; acc[2][1] += a2 * bb.y; acc[2][2] += a2 * bb.z; acc[2][3] += a2 * bb.w;
            acc[3][0] += a3 * bb.x; acc[3][1] += a3 * bb.y; acc[3][2] += a3 * bb.z; acc[3][3] += a3 * bb.w;
        }
        __syncthreads();
    }

#pragma unroll
    for (int i = 0; i < 4; i++) {
        float4 r = make_float4(acc[i][0], acc[i][1], acc[i][2], acc[i][3]);
        *(float4*)&Y[(size_t)(m0 + ty * 4 + i) * HH + tx * 4] = r;
    }
}

// ---------------- K2: recurrent scan ----------------
// grid = 32 batches * 4 j-splits = 128 blocks, 256 threads.
// thread layout: jj = tid>>4 (16 local j), strip = tid&15, i0 = strip*4.
// Each thread holds S[i0..i0+3][j] (4 state floats).
// Per timestep t: S *= (done? 0 : kappa); per agent a:
//   S += k_a(i) * v_a(j);  O_a[j] = sum_i q_a(i)*S(i,j)  (shfl-reduce 16 lanes)
#define CH 8   // timesteps staged in smem per chunk
__global__ __launch_bounds__(256)
void scan_kernel(const float* __restrict__ hstate,
                 float* __restrict__ out,
                 int write_h) {
    const int b = blockIdx.x >> 2;
    const int jblk = blockIdx.x & 3;
    const int jbase = jblk * 16;

    const int tid = threadIdx.x;
    const int jj = tid >> 4;
    const int j = jbase + jj;
    const int strip = tid & 15;
    const int i0 = strip * 4;

    __shared__ float q_sm[CH * 4 * HH];   // 2048 floats
    __shared__ float k_sm[CH * 4 * HH];
    __shared__ float v_sm[CH * 4 * HH];

    float S[4];
#pragma unroll
    for (int ii = 0; ii < 4; ii++)
        S[ii] = hstate[(size_t)b * HH * HH + (i0 + ii) * HH + j];

    const size_t base = (size_t)b * SS * HH;   // linear offset into g_q/g_k/g_v
    const unsigned char* tsd = &g_tsdone[b * TT];

    for (int tc = 0; tc < TT / CH; tc++) {
        // stage chunk: 2048 consecutive floats per array (layout is linear in (s,h))
        const size_t coff = base + (size_t)tc * (CH * 4 * HH);
        __syncthreads();
#pragma unroll
        for (int r = 0; r < 2; r++) {
            int i4 = tid + r * 256;            // 512 float4 per array
            *(float4*)&q_sm[i4 * 4] = *(const float4*)&g_q[coff + i4 * 4];
            *(float4*)&k_sm[i4 * 4] = *(const float4*)&g_k[coff + i4 * 4];
            *(float4*)&v_sm[i4 * 4] = *(const float4*)&g_v[coff + i4 * 4];
        }
        __syncthreads();

#pragma unroll
        for (int tl = 0; tl < CH; tl++) {
            const int t = tc * CH + tl;
            const float scale = tsd[t] ? 0.f : KAPPA;
            S[0] *= scale; S[1] *= scale; S[2] *= scale; S[3] *= scale;

#pragma unroll
            for (int a = 0; a < 4; a++) {
                const int sl = tl * 4 + a;
                float4 kv = *(const float4*)&k_sm[sl * HH + i0];
                float4 qv = *(const float4*)&q_sm[sl * HH + i0];
                float vj = v_sm[sl * HH + j];
                S[0] += kv.x * vj;
                S[1] += kv.y * vj;
                S[2] += kv.z * vj;
                S[3] += kv.w * vj;
                float acc = qv.x * S[0] + qv.y * S[1] + qv.z * S[2] + qv.w * S[3];
                // reduce over the 16 lanes sharing this j (consecutive lanes)
                acc += __shfl_xor_sync(0xffffffffu, acc, 1);
                acc += __shfl_xor_sync(0xffffffffu, acc, 2);
                acc += __shfl_xor_sync(0xffffffffu, acc, 4);
                acc += __shfl_xor_sync(0xffffffffu, acc, 8);
                if (strip == a)
                    out[base + (size_t)(tc * CH * 4 + sl) * HH + j] = acc;
            }
        }
    }

    if (write_h) {
        float* h_out = out + (size_t)BB * SS * HH + (size_t)b * HH * HH;
#pragma unroll
        for (int ii = 0; ii < 4; ii++)
            h_out[(i0 + ii) * HH + j] = S[ii];
    }
}

// ---------------- host launcher ----------------
extern "C" void kernel_launch(void* const* d_in, const int* in_sizes, int n_in,
                              void* d_out, int out_size) {
    const float* key    = (const float*)d_in[0];
    const float* query  = (const float*)d_in[1];
    const float* value  = (const float*)d_in[2];
    const float* hstate = (const float*)d_in[3];
    const void*  dones  = d_in[4];
    const float* Wq     = (const float*)d_in[5];
    const float* Wk     = (const float*)d_in[6];
    const float* Wv     = (const float*)d_in[7];
    float* out = (float*)d_out;

    int write_h = (out_size >= BB * SS * HH + BB * HH * HH) ? 1 : 0;

    decode_dones_kernel<<<1, 256>>>(dones);
    dim3 pg(SS * BB / 64, 1, 3);   // 512 x 1 x 3
    proj_kernel<<<pg, 256>>>(key, query, value, Wq, Wk, Wv);
    scan_kernel<<<BB * 4, 256>>>(hstate, out, write_h);
}

// round 3
// speedup vs baseline: 1.2064x; 1.2064x over previous
#include <cuda_runtime.h>
#include <cuda_bf16.h>
#include <cstdint>

// SimpleRetention — recurrent reformulation + split-bf16 tensor-core projections.
// B=32, S=1024, E=512, H=64, N_AGENTS=4, T=256, KAPPA=0.9

#define BB 32
#define SS 1024
#define EE 512
#define HH 64
#define TT 256
#define KAPPA 0.9f

// ---------------- device scratch ----------------
__device__ float g_q[BB * SS * HH];
__device__ float g_k[BB * SS * HH];
__device__ float g_v[BB * SS * HH];
__device__ unsigned char g_tsdone[BB * TT];

// ---------------- K0: decode dones (dtype-agnostic) ----------------
__global__ void decode_dones_kernel(const void* __restrict__ dones) {
    __shared__ int s_f32, s_u8;
    if (threadIdx.x == 0) { s_f32 = 0; s_u8 = 0; }
    __syncthreads();
    const unsigned* w = (const unsigned*)dones;
    int lf = 0, lu = 0;
    for (int idx = threadIdx.x; idx < 8192; idx += 512) {
        unsigned x = w[idx];
        if (x == 0x3F800000u) lf = 1;
        else if (x > 1u) lu = 1;   // multi-byte packing => uint8
    }
    if (lf) s_f32 = 1;
    if (lu) s_u8 = 1;
    __syncthreads();
    int fmt = s_f32 ? 1 : (s_u8 ? 2 : 0);  // 0=int32, 1=float32, 2=uint8

    for (int idx = threadIdx.x; idx < BB * TT; idx += 512) {
        int b = idx >> 8;
        int t = idx & 255;
        int pos = b * SS + 4 * t;
        unsigned char d;
        if (fmt == 2) d = (((const unsigned char*)dones)[pos] != 0);
        else          d = (w[pos] != 0u);
        g_tsdone[idx] = d;
    }
}

// ---------------- K1: split-bf16 tensor-core projection ----------------
// Y[32768,64] = X[32768,512] @ W[512,64], fp32 accuracy via 3-term bf16 split.
// BM=128, KC=32, 256 threads (8 warps), warp w -> rows w*16..w*16+15, all 64 cols.

#define BM 128
#define KC 32
#define XSTR 34   // row stride in bf16 elems (68B = 17 banks -> conflict-free)

__device__ __forceinline__ void mma16816(float& c0, float& c1, float& c2, float& c3,
                                         uint32_t a0, uint32_t a1, uint32_t a2, uint32_t a3,
                                         uint32_t b0, uint32_t b1) {
    asm volatile(
        "mma.sync.aligned.m16n8k16.row.col.f32.bf16.bf16.f32 "
        "{%0,%1,%2,%3}, {%4,%5,%6,%7}, {%8,%9}, {%0,%1,%2,%3};\n"
        : "+f"(c0), "+f"(c1), "+f"(c2), "+f"(c3)
        : "r"(a0), "r"(a1), "r"(a2), "r"(a3), "r"(b0), "r"(b1));
}

__global__ __launch_bounds__(256)
void proj_kernel(const float* __restrict__ in_key,
                 const float* __restrict__ in_query,
                 const float* __restrict__ in_value,
                 const float* __restrict__ Wq,
                 const float* __restrict__ Wk,
                 const float* __restrict__ Wv) {
    const float* X;
    const float* W;
    float* Y;
    switch (blockIdx.z) {
        case 0:  X = in_query; W = Wq; Y = g_q; break;
        case 1:  X = in_key;   W = Wk; Y = g_k; break;
        default: X = in_value; W = Wv; Y = g_v; break;
    }

    __shared__ __nv_bfloat16 Xh[BM * XSTR];   // 8704 B
    __shared__ __nv_bfloat16 Xl[BM * XSTR];
    __shared__ __nv_bfloat16 Wh[HH * XSTR];   // [n][k] transposed, 4352 B
    __shared__ __nv_bfloat16 Wl[HH * XSTR];

    const int tid  = threadIdx.x;
    const int wid  = tid >> 5;
    const int lane = tid & 31;
    const int g    = lane >> 2;      // group 0..7
    const int t    = lane & 3;       // thread-in-group
    const int m0   = blockIdx.x * BM;
    const int m0w  = wid * 16;       // warp row base within tile

    float c[8][4];
#pragma unroll
    for (int nt = 0; nt < 8; nt++)
#pragma unroll
        for (int e = 0; e < 4; e++) c[nt][e] = 0.f;

    for (int kt = 0; kt < EE; kt += KC) {
        __syncthreads();   // previous chunk fully consumed
        // ---- stage X chunk: 128 rows x 32 floats = 1024 float4 ----
#pragma unroll
        for (int r = 0; r < 4; r++) {
            int i4  = tid + r * 256;
            int row = i4 >> 3;
            int c4  = (i4 & 7) * 4;
            float4 xv = *(const float4*)&X[(size_t)(m0 + row) * EE + kt + c4];
            float xs[4] = {xv.x, xv.y, xv.z, xv.w};
            __nv_bfloat16 h[4], l[4];
#pragma unroll
            for (int e = 0; e < 4; e++) {
                h[e] = __float2bfloat16_rn(xs[e]);
                l[e] = __float2bfloat16_rn(xs[e] - __bfloat162float(h[e]));
            }
            int base = row * XSTR + c4;
            *(__nv_bfloat162*)&Xh[base + 0] = __nv_bfloat162(h[0], h[1]);
            *(__nv_bfloat162*)&Xh[base + 2] = __nv_bfloat162(h[2], h[3]);
            *(__nv_bfloat162*)&Xl[base + 0] = __nv_bfloat162(l[0], l[1]);
            *(__nv_bfloat162*)&Xl[base + 2] = __nv_bfloat162(l[2], l[3]);
        }
        // ---- stage W chunk transposed: 32 k-rows x 64 n = 512 float4 ----
#pragma unroll
        for (int r = 0; r < 2; r++) {
            int i4   = tid + r * 256;
            int krow = i4 >> 4;            // 0..31
            int c4   = (i4 & 15) * 4;      // n base
            float4 wv = *(const float4*)&W[(size_t)(kt + krow) * HH + c4];
            float ws[4] = {wv.x, wv.y, wv.z, wv.w};
#pragma unroll
            for (int e = 0; e < 4; e++) {
                __nv_bfloat16 h = __float2bfloat16_rn(ws[e]);
                __nv_bfloat16 l = __float2bfloat16_rn(ws[e] - __bfloat162float(h));
                Wh[(c4 + e) * XSTR + krow] = h;
                Wl[(c4 + e) * XSTR + krow] = l;
            }
        }
        __syncthreads();

        // ---- compute: 2 k-steps of 16 ----
#pragma unroll
        for (int ks = 0; ks < 2; ks++) {
            const int kb = ks * 16;
            const int ra = (m0w + g) * XSTR + kb + t * 2;
            uint32_t ah0 = *(const uint32_t*)&Xh[ra];
            uint32_t ah1 = *(const uint32_t*)&Xh[ra + 8 * XSTR];
            uint32_t ah2 = *(const uint32_t*)&Xh[ra + 8];
            uint32_t ah3 = *(const uint32_t*)&Xh[ra + 8 * XSTR + 8];
            uint32_t al0 = *(const uint32_t*)&Xl[ra];
            uint32_t al1 = *(const uint32_t*)&Xl[ra + 8 * XSTR];
            uint32_t al2 = *(const uint32_t*)&Xl[ra + 8];
            uint32_t al3 = *(const uint32_t*)&Xl[ra + 8 * XSTR + 8];
#pragma unroll
            for (int nt = 0; nt < 8; nt++) {
                const int rb = (nt * 8 + g) * XSTR + kb + t * 2;
                uint32_t bh0 = *(const uint32_t*)&Wh[rb];
                uint32_t bh1 = *(const uint32_t*)&Wh[rb + 8];
                uint32_t bl0 = *(const uint32_t*)&Wl[rb];
                uint32_t bl1 = *(const uint32_t*)&Wl[rb + 8];
                mma16816(c[nt][0], c[nt][1], c[nt][2], c[nt][3],
                         ah0, ah1, ah2, ah3, bh0, bh1);
                mma16816(c[nt][0], c[nt][1], c[nt][2], c[nt][3],
                         ah0, ah1, ah2, ah3, bl0, bl1);
                mma16816(c[nt][0], c[nt][1], c[nt][2], c[nt][3],
                         al0, al1, al2, al3, bh0, bh1);
            }
        }
    }

    // ---- epilogue: C frag -> gmem ----
#pragma unroll
    for (int nt = 0; nt < 8; nt++) {
        const int col = nt * 8 + t * 2;
        const size_t r0 = (size_t)(m0 + m0w + g) * HH + col;
        const size_t r1 = (size_t)(m0 + m0w + g + 8) * HH + col;
        *(float2*)&Y[r0] = make_float2(c[nt][0], c[nt][1]);
        *(float2*)&Y[r1] = make_float2(c[nt][2], c[nt][3]);
    }
}

// ---------------- K2: recurrent scan (unchanged, validated) ----------------
#define CH 8
__global__ __launch_bounds__(256)
void scan_kernel(const float* __restrict__ hstate,
                 float* __restrict__ out,
                 int write_h) {
    const int b = blockIdx.x >> 2;
    const int jblk = blockIdx.x & 3;
    const int jbase = jblk * 16;

    const int tid = threadIdx.x;
    const int jj = tid >> 4;
    const int j = jbase + jj;
    const int strip = tid & 15;
    const int i0 = strip * 4;

    __shared__ float q_sm[CH * 4 * HH];
    __shared__ float k_sm[CH * 4 * HH];
    __shared__ float v_sm[CH * 4 * HH];

    float S[4];
#pragma unroll
    for (int ii = 0; ii < 4; ii++)
        S[ii] = hstate[(size_t)b * HH * HH + (i0 + ii) * HH + j];

    const size_t base = (size_t)b * SS * HH;
    const unsigned char* tsd = &g_tsdone[b * TT];

    for (int tc = 0; tc < TT / CH; tc++) {
        const size_t coff = base + (size_t)tc * (CH * 4 * HH);
        __syncthreads();
#pragma unroll
        for (int r = 0; r < 2; r++) {
            int i4 = tid + r * 256;
            *(float4*)&q_sm[i4 * 4] = *(const float4*)&g_q[coff + i4 * 4];
            *(float4*)&k_sm[i4 * 4] = *(const float4*)&g_k[coff + i4 * 4];
            *(float4*)&v_sm[i4 * 4] = *(const float4*)&g_v[coff + i4 * 4];
        }
        __syncthreads();

#pragma unroll
        for (int tl = 0; tl < CH; tl++) {
            const int tglob = tc * CH + tl;
            const float scale = tsd[tglob] ? 0.f : KAPPA;
            S[0] *= scale; S[1] *= scale; S[2] *= scale; S[3] *= scale;

#pragma unroll
            for (int a = 0; a < 4; a++) {
                const int sl = tl * 4 + a;
                float4 kv = *(const float4*)&k_sm[sl * HH + i0];
                float4 qv = *(const float4*)&q_sm[sl * HH + i0];
                float vj = v_sm[sl * HH + j];
                S[0] += kv.x * vj;
                S[1] += kv.y * vj;
                S[2] += kv.z * vj;
                S[3] += kv.w * vj;
                float acc = qv.x * S[0] + qv.y * S[1] + qv.z * S[2] + qv.w * S[3];
                acc += __shfl_xor_sync(0xffffffffu, acc, 1);
                acc += __shfl_xor_sync(0xffffffffu, acc, 2);
                acc += __shfl_xor_sync(0xffffffffu, acc, 4);
                acc += __shfl_xor_sync(0xffffffffu, acc, 8);
                if (strip == a)
                    out[base + (size_t)(tc * CH * 4 + sl) * HH + j] = acc;
            }
        }
    }

    if (write_h) {
        float* h_out = out + (size_t)BB * SS * HH + (size_t)b * HH * HH;
#pragma unroll
        for (int ii = 0; ii < 4; ii++)
            h_out[(i0 + ii) * HH + j] = S[ii];
    }
}

// ---------------- host launcher ----------------
extern "C" void kernel_launch(void* const* d_in, const int* in_sizes, int n_in,
                              void* d_out, int out_size) {
    const float* key    = (const float*)d_in[0];
    const float* query  = (const float*)d_in[1];
    const float* value  = (const float*)d_in[2];
    const float* hstate = (const float*)d_in[3];
    const void*  dones  = d_in[4];
    const float* Wq     = (const float*)d_in[5];
    const float* Wk     = (const float*)d_in[6];
    const float* Wv     = (const float*)d_in[7];
    float* out = (float*)d_out;

    int write_h = (out_size >= BB * SS * HH + BB * HH * HH) ? 1 : 0;

    decode_dones_kernel<<<1, 512>>>(dones);
    dim3 pg(SS * BB / BM, 1, 3);   // 256 x 1 x 3
    proj_kernel<<<pg, 256>>>(key, query, value, Wq, Wk, Wv);
    scan_kernel<<<BB * 4, 256>>>(hstate, out, write_h);
}

// round 5
// speedup vs baseline: 1.4122x; 1.1706x over previous
#include <cuda_runtime.h>
#include <cuda_bf16.h>
#include <cstdint>

// SimpleRetention — recurrent reformulation + split-bf16 tensor-core projections.
// B=32, S=1024, E=512, H=64, N_AGENTS=4, T=256, KAPPA=0.9

#define BB 32
#define SS 1024
#define EE 512
#define HH 64
#define TT 256
#define KAPPA 0.9f

// ---------------- device scratch ----------------
__device__ float g_q[BB * SS * HH];
__device__ float g_k[BB * SS * HH];
__device__ float g_v[BB * SS * HH];
__device__ int g_fmt;                          // 0=int32, 1=float32, 2=uint8
__device__ __nv_bfloat16 g_Wh[3 * HH * EE];    // split weights, [z][n][k]
__device__ __nv_bfloat16 g_Wl[3 * HH * EE];

// truncation split: hi = top-16-bits(x) as bf16, lo = bf16_trunc(x - hi)
__device__ __forceinline__ unsigned hi_mask(float x) {
    return __float_as_uint(x) & 0xFFFF0000u;
}

// ---------------- K0: prep (detect dones fmt + transpose/split W) ----------------
__global__ __launch_bounds__(256)
void prep_kernel(const void* __restrict__ dones,
                 const float* __restrict__ Wq,
                 const float* __restrict__ Wk,
                 const float* __restrict__ Wv) {
    const int tid = threadIdx.x;
    if (blockIdx.x == 0) {
        // ---- detect dtype of dones over first 8192 words (32 KB, min size) ----
        __shared__ int s_f32, s_u8;
        if (tid == 0) { s_f32 = 0; s_u8 = 0; }
        __syncthreads();
        const uint4* w4 = (const uint4*)dones;
        int lf = 0, lu = 0;
#pragma unroll
        for (int r = 0; r < 8; r++) {           // 256 thr * 8 = 2048 uint4 = 8192 words
            uint4 v = w4[tid + r * 256];
            unsigned a[4] = {v.x, v.y, v.z, v.w};
#pragma unroll
            for (int e = 0; e < 4; e++) {
                if (a[e] == 0x3F800000u) lf = 1;
                else if (a[e] > 1u) lu = 1;     // multi-byte packing => uint8
            }
        }
        if (lf) s_f32 = 1;
        if (lu) s_u8 = 1;
        __syncthreads();
        if (tid == 0) g_fmt = s_f32 ? 1 : (s_u8 ? 2 : 0);
    } else {
        // ---- transpose + split one W matrix: [512][64] f32 -> [64][512] bf16 x2 ----
        const int z = blockIdx.x - 1;
        const float* W = (z == 0) ? Wq : (z == 1) ? Wk : Wv;
        __nv_bfloat16* Wh = &g_Wh[z * HH * EE];
        __nv_bfloat16* Wl = &g_Wl[z * HH * EE];
        __shared__ float tile[64][65];
        for (int kt = 0; kt < 8; kt++) {
#pragma unroll
            for (int r = 0; r < 16; r++) {
                int idx = tid + r * 256;
                int row = idx >> 6, col = idx & 63;
                tile[row][col] = W[(size_t)(kt * 64 + row) * HH + col];
            }
            __syncthreads();
#pragma unroll
            for (int r = 0; r < 16; r++) {
                int idx = tid + r * 256;
                int n = idx >> 6, kl = idx & 63;
                float x = tile[kl][n];
                unsigned hb = hi_mask(x);
                float lo = x - __uint_as_float(hb);
                unsigned lb = __float_as_uint(lo);
                size_t o = (size_t)n * EE + kt * 64 + kl;
                Wh[o] = __ushort_as_bfloat16((unsigned short)(hb >> 16));
                Wl[o] = __ushort_as_bfloat16((unsigned short)(lb >> 16));
            }
            __syncthreads();
        }
    }
}

// ---------------- K1: split-bf16 tensor-core projection ----------------
// Y[32768,64] = X[32768,512] @ W[512,64].  BM=128, KC=32, 256 threads (8 warps).
#define BM 128
#define KC 32
#define XSTR 40   // row stride in bf16 elems (80 B = 20 banks) -> conflict-free frags
#define WSTR 40

__device__ __forceinline__ void mma16816(float& c0, float& c1, float& c2, float& c3,
                                         uint32_t a0, uint32_t a1, uint32_t a2, uint32_t a3,
                                         uint32_t b0, uint32_t b1) {
    asm volatile(
        "mma.sync.aligned.m16n8k16.row.col.f32.bf16.bf16.f32 "
        "{%0,%1,%2,%3}, {%4,%5,%6,%7}, {%8,%9}, {%0,%1,%2,%3};\n"
        : "+f"(c0), "+f"(c1), "+f"(c2), "+f"(c3)
        : "r"(a0), "r"(a1), "r"(a2), "r"(a3), "r"(b0), "r"(b1));
}

__global__ __launch_bounds__(256)
void proj_kernel(const float* __restrict__ in_key,
                 const float* __restrict__ in_query,
                 const float* __restrict__ in_value) {
    const float* X;
    float* Y;
    switch (blockIdx.z) {
        case 0:  X = in_query; Y = g_q; break;
        case 1:  X = in_key;   Y = g_k; break;
        default: X = in_value; Y = g_v; break;
    }
    const __nv_bfloat16* Wh = &g_Wh[blockIdx.z * HH * EE];
    const __nv_bfloat16* Wl = &g_Wl[blockIdx.z * HH * EE];

    __shared__ __nv_bfloat16 Xh[BM * XSTR];   // 10240 B
    __shared__ __nv_bfloat16 Xl[BM * XSTR];
    __shared__ __nv_bfloat16 Whs[HH * WSTR];  // 5120 B
    __shared__ __nv_bfloat16 Wls[HH * WSTR];

    const int tid  = threadIdx.x;
    const int wid  = tid >> 5;
    const int lane = tid & 31;
    const int g    = lane >> 2;
    const int t    = lane & 3;
    const int m0   = blockIdx.x * BM;
    const int m0w  = wid * 16;

    // per-thread staging coordinates
    const int xrow = tid >> 3;            // 0..31 (x4 over r)
    const int xc4  = (tid & 7) * 4;       // k offset
    const int wrow = tid >> 2;            // 0..63
    const int wseg = (tid & 3) * 8;       // k offset (8 bf16 per uint4)

    float c[8][4];
#pragma unroll
    for (int nt = 0; nt < 8; nt++)
#pragma unroll
        for (int e = 0; e < 4; e++) c[nt][e] = 0.f;

    // ---- prologue: prefetch chunk 0 ----
    float4 xr[4];
    uint4 whr, wlr;
#pragma unroll
    for (int r = 0; r < 4; r++)
        xr[r] = *(const float4*)&X[(size_t)(m0 + xrow + r * 32) * EE + xc4];
    whr = *(const uint4*)&Wh[(size_t)wrow * EE + wseg];
    wlr = *(const uint4*)&Wl[(size_t)wrow * EE + wseg];

    for (int kt = 0; kt < EE; kt += KC) {
        // ---- stage prefetched regs into smem (with X split) ----
#pragma unroll
        for (int r = 0; r < 4; r++) {
            int row = xrow + r * 32;
            float xs[4] = {xr[r].x, xr[r].y, xr[r].z, xr[r].w};
            unsigned hb[4], lb[4];
#pragma unroll
            for (int e = 0; e < 4; e++) {
                hb[e] = hi_mask(xs[e]);
                lb[e] = __float_as_uint(xs[e] - __uint_as_float(hb[e]));
            }
            int base = row * XSTR + xc4;
            uint2 ph = make_uint2(__byte_perm(hb[0], hb[1], 0x7632),
                                  __byte_perm(hb[2], hb[3], 0x7632));
            uint2 pl = make_uint2(__byte_perm(lb[0], lb[1], 0x7632),
                                  __byte_perm(lb[2], lb[3], 0x7632));
            *(uint2*)&Xh[base] = ph;
            *(uint2*)&Xl[base] = pl;
        }
        *(uint4*)&Whs[wrow * WSTR + wseg] = whr;
        *(uint4*)&Wls[wrow * WSTR + wseg] = wlr;
        __syncthreads();

        // ---- prefetch next chunk (overlaps with MMAs below) ----
        if (kt + KC < EE) {
#pragma unroll
            for (int r = 0; r < 4; r++)
                xr[r] = *(const float4*)&X[(size_t)(m0 + xrow + r * 32) * EE + kt + KC + xc4];
            whr = *(const uint4*)&Wh[(size_t)wrow * EE + kt + KC + wseg];
            wlr = *(const uint4*)&Wl[(size_t)wrow * EE + kt + KC + wseg];
        }

        // ---- compute: 2 k-steps of 16 ----
#pragma unroll
        for (int ks = 0; ks < 2; ks++) {
            const int kb = ks * 16;
            const int ra = (m0w + g) * XSTR + kb + t * 2;
            uint32_t ah0 = *(const uint32_t*)&Xh[ra];
            uint32_t ah1 = *(const uint32_t*)&Xh[ra + 8 * XSTR];
            uint32_t ah2 = *(const uint32_t*)&Xh[ra + 8];
            uint32_t ah3 = *(const uint32_t*)&Xh[ra + 8 * XSTR + 8];
            uint32_t al0 = *(const uint32_t*)&Xl[ra];
            uint32_t al1 = *(const uint32_t*)&Xl[ra + 8 * XSTR];
            uint32_t al2 = *(const uint32_t*)&Xl[ra + 8];
            uint32_t al3 = *(const uint32_t*)&Xl[ra + 8 * XSTR + 8];
#pragma unroll
            for (int nt = 0; nt < 8; nt++) {
                const int rb = (nt * 8 + g) * WSTR + kb + t * 2;
                uint32_t bh0 = *(const uint32_t*)&Whs[rb];
                uint32_t bh1 = *(const uint32_t*)&Whs[rb + 8];
                uint32_t bl0 = *(const uint32_t*)&Wls[rb];
                uint32_t bl1 = *(const uint32_t*)&Wls[rb + 8];
                mma16816(c[nt][0], c[nt][1], c[nt][2], c[nt][3],
                         ah0, ah1, ah2, ah3, bh0, bh1);
                mma16816(c[nt][0], c[nt][1], c[nt][2], c[nt][3],
                         ah0, ah1, ah2, ah3, bl0, bl1);
                mma16816(c[nt][0], c[nt][1], c[nt][2], c[nt][3],
                         al0, al1, al2, al3, bh0, bh1);
            }
        }
        __syncthreads();
    }

    // ---- epilogue ----
#pragma unroll
    for (int nt = 0; nt < 8; nt++) {
        const int col = nt * 8 + t * 2;
        const size_t r0 = (size_t)(m0 + m0w + g) * HH + col;
        const size_t r1 = (size_t)(m0 + m0w + g + 8) * HH + col;
        *(float2*)&Y[r0] = make_float2(c[nt][0], c[nt][1]);
        *(float2*)&Y[r1] = make_float2(c[nt][2], c[nt][3]);
    }
}

// ---------------- K2: recurrent scan (dones decode fused in) ----------------
#define CH 8
__global__ __launch_bounds__(256)
void scan_kernel(const float* __restrict__ hstate,
                 const void* __restrict__ dones,
                 float* __restrict__ out,
                 int write_h) {
    const int b = blockIdx.x >> 2;
    const int jblk = blockIdx.x & 3;
    const int jbase = jblk * 16;

    const int tid = threadIdx.x;
    const int jj = tid >> 4;
    const int j = jbase + jj;
    const int strip = tid & 15;
    const int i0 = strip * 4;

    __shared__ float q_sm[CH * 4 * HH];
    __shared__ float k_sm[CH * 4 * HH];
    __shared__ float v_sm[CH * 4 * HH];
    __shared__ float sc[TT];   // per-timestep decay scale

    // decode this batch's dones (fmt detected by prep kernel)
    {
        const int fmt = g_fmt;
        const int pos = b * SS + 4 * tid;   // tid 0..255 == timestep
        bool d;
        if (fmt == 2) d = ((const unsigned char*)dones)[pos] != 0;
        else          d = ((const unsigned*)dones)[pos] != 0u;
        sc[tid] = d ? 0.f : KAPPA;
    }

    float S[4];
#pragma unroll
    for (int ii = 0; ii < 4; ii++)
        S[ii] = hstate[(size_t)b * HH * HH + (i0 + ii) * HH + j];

    const size_t base = (size_t)b * SS * HH;

    for (int tc = 0; tc < TT / CH; tc++) {
        const size_t coff = base + (size_t)tc * (CH * 4 * HH);
        __syncthreads();
#pragma unroll
        for (int r = 0; r < 2; r++) {
            int i4 = tid + r * 256;
            *(float4*)&q_sm[i4 * 4] = *(const float4*)&g_q[coff + i4 * 4];
            *(float4*)&k_sm[i4 * 4] = *(const float4*)&g_k[coff + i4 * 4];
            *(float4*)&v_sm[i4 * 4] = *(const float4*)&g_v[coff + i4 * 4];
        }
        __syncthreads();

#pragma unroll
        for (int tl = 0; tl < CH; tl++) {
            const float scale = sc[tc * CH + tl];
            S[0] *= scale; S[1] *= scale; S[2] *= scale; S[3] *= scale;

#pragma unroll
            for (int a = 0; a < 4; a++) {
                const int sl = tl * 4 + a;
                float4 kv = *(const float4*)&k_sm[sl * HH + i0];
                float4 qv = *(const float4*)&q_sm[sl * HH + i0];
                float vj = v_sm[sl * HH + j];
                S[0] += kv.x * vj;
                S[1] += kv.y * vj;
                S[2] += kv.z * vj;
                S[3] += kv.w * vj;
                float acc = qv.x * S[0] + qv.y * S[1] + qv.z * S[2] + qv.w * S[3];
                acc += __shfl_xor_sync(0xffffffffu, acc, 1);
                acc += __shfl_xor_sync(0xffffffffu, acc, 2);
                acc += __shfl_xor_sync(0xffffffffu, acc, 4);
                acc += __shfl_xor_sync(0xffffffffu, acc, 8);
                if (strip == a)
                    out[base + (size_t)(tc * CH * 4 + sl) * HH + j] = acc;
            }
        }
    }

    if (write_h) {
        float* h_out = out + (size_t)BB * SS * HH + (size_t)b * HH * HH;
#pragma unroll
        for (int ii = 0; ii < 4; ii++)
            h_out[(i0 + ii) * HH + j] = S[ii];
    }
}

// ---------------- host launcher ----------------
extern "C" void kernel_launch(void* const* d_in, const int* in_sizes, int n_in,
                              void* d_out, int out_size) {
    const float* key    = (const float*)d_in[0];
    const float* query  = (const float*)d_in[1];
    const float* value  = (const float*)d_in[2];
    const float* hstate = (const float*)d_in[3];
    const void*  dones  = d_in[4];
    const float* Wq     = (const float*)d_in[5];
    const float* Wk     = (const float*)d_in[6];
    const float* Wv     = (const float*)d_in[7];
    float* out = (float*)d_out;

    int write_h = (out_size >= BB * SS * HH + BB * HH * HH) ? 1 : 0;

    prep_kernel<<<4, 256>>>(dones, Wq, Wk, Wv);
    dim3 pg(SS * BB / BM, 1, 3);   // 256 x 1 x 3
    proj_kernel<<<pg, 256>>>(key, query, value);
    scan_kernel<<<BB * 4, 256>>>(hstate, dones, out, write_h);
}